// round 15
// baseline (speedup 1.0000x reference)
#include <cuda_runtime.h>
#include <cuda_bf16.h>
#include <cstdint>
#include <math.h>
#include <mma.h>

using namespace nvcuda;

// ---------------------------------------------------------------------------
// ScaffoldGAN JTNN GRU + discriminator. R15: bf16 HMMA GEMM with K-chunk 16,
// 3-stage cp.async ring, ONE __syncthreads per stage, __launch_bounds__(256,4)
// -> 4 blocks/SM (R14: occ capped at 3 blocks, tensor 44%). zero_kernel
// deleted (step0 emits zeros when depth<1; pads provably inert).
// ---------------------------------------------------------------------------

#define HH     450
#define NNODES 4000
#define NMESS  6000
#define KNB    6
#define BB     256
#define DHH    450
#define MAXDEPTH 15
#define MROWS  6016

#define LDX   512
#define LDZU  1024
#define LDPRE 1536

#define KC     16         // K chunk
#define NT2    30         // 480 / 16
#define KPADB  24         // bf16 elems per smem row (48 B)
#define AOP    6144       // 128*KPADB*2 bytes, one A operand per stage
#define BOP    3072       // 64*KPADB*2
#define STAGE  18432      // Ahi+Alo+Bhi+Blo
#define SMTOT  55296      // 3 stages; epilogue Cs (128*68*4=34816) fits

// ---------------- device scratch (zero-initialized; pads never written) ----
__device__ float g_fe[NNODES * HH];
__device__ float g_xzrh[MROWS * LDPRE];   // (xz+bz) | (xh+bh) | (xr+bUr)
__device__ float g_h[MROWS * LDX];
__device__ float g_hZU[MROWS * LDZU];
__device__ float g_sumh[MROWS * LDX];
__device__ float g_z[MROWS * LDX];
__device__ float g_bias[1536];
__device__ float g_rv[BB * 2 * HH];
__device__ float g_d1[BB * DHH];
__device__ float g_d2[BB * DHH];
__device__ __nv_bfloat16 g_xhi[MROWS * LDX];
__device__ __nv_bfloat16 g_xlo[MROWS * LDX];
__device__ __nv_bfloat16 g_hhi[MROWS * LDX];
__device__ __nv_bfloat16 g_hlo[MROWS * LDX];
__device__ __nv_bfloat16 g_sghi[MROWS * LDX];
__device__ __nv_bfloat16 g_sglo[MROWS * LDX];
__device__ __nv_bfloat16 g_Wpre_hi[1408 * LDX];
__device__ __nv_bfloat16 g_Wpre_lo[1408 * LDX];
__device__ __nv_bfloat16 g_Wstep_hi[1024 * LDX];
__device__ __nv_bfloat16 g_Wstep_lo[1024 * LDX];
__device__ __nv_bfloat16 g_Whh_hi[512 * LDX];
__device__ __nv_bfloat16 g_Whh_lo[512 * LDX];

// --------------------------- helpers ---------------------------------------
__device__ __forceinline__ uint32_t smem_u32(const void* p) {
    uint32_t a;
    asm("{ .reg .u64 t; cvta.to.shared.u64 t, %1; cvt.u32.u64 %0, t; }"
        : "=r"(a) : "l"(p));
    return a;
}
#define CP16(d, s) \
    asm volatile("cp.async.cg.shared.global [%0], [%1], 16;" \
                 :: "r"(d), "l"(s) : "memory")
#define CP_COMMIT asm volatile("cp.async.commit_group;" ::: "memory")
#define CP_WAIT1  asm volatile("cp.async.wait_group 1;" ::: "memory")
#define CP_WAIT0  asm volatile("cp.async.wait_group 0;" ::: "memory")

__device__ __forceinline__ void split1(float v, __nv_bfloat16& hi, __nv_bfloat16& lo) {
    hi = __float2bfloat16(v);
    lo = __float2bfloat16(v - __bfloat162float(hi));
}
__device__ __forceinline__ float2 sigm2(float2 v) {
    return make_float2(1.f / (1.f + __expf(-v.x)), 1.f / (1.f + __expf(-v.y)));
}
__device__ __forceinline__ float2 tanh2(float2 v) {
    return make_float2(tanhf(v.x), tanhf(v.y));
}

// ---------------------------- small kernels --------------------------------
__global__ void pack_kernel(const float* __restrict__ W_z_w,
                            const float* __restrict__ W_h_w,
                            const float* __restrict__ W_r_w,
                            const float* __restrict__ U_r_w,
                            const float* __restrict__ W_z_b,
                            const float* __restrict__ W_h_b,
                            const float* __restrict__ U_r_b,
                            __nv_bfloat16* __restrict__ Wpre_hi,
                            __nv_bfloat16* __restrict__ Wpre_lo,
                            __nv_bfloat16* __restrict__ Wstep_hi,
                            __nv_bfloat16* __restrict__ Wstep_lo,
                            __nv_bfloat16* __restrict__ Whh_hi,
                            __nv_bfloat16* __restrict__ Whh_lo,
                            float* __restrict__ bias) {
    int i = blockIdx.x * blockDim.x + threadIdx.x;
    const int NPRE  = 1350 * HH;
    const int NSTEP = 900 * HH;
    const int NWHH  = HH * HH;
    if (i < NPRE) {
        int n = i / HH, k = i - n * HH;
        float v;
        if (n < HH)            v = W_z_w[n * 2 * HH + k];
        else if (n < 2 * HH)   v = W_h_w[(n - HH) * 2 * HH + k];
        else                   v = W_r_w[(n - 2 * HH) * HH + k];
        split1(v, Wpre_hi[n * LDX + k], Wpre_lo[n * LDX + k]);
    } else if (i < NPRE + NSTEP) {
        int j = i - NPRE;
        int n = j / HH, k = j - n * HH;
        float v = (n < HH) ? W_z_w[n * 2 * HH + HH + k]
                           : U_r_w[(n - HH) * HH + k];
        split1(v, Wstep_hi[n * LDX + k], Wstep_lo[n * LDX + k]);
    } else if (i < NPRE + NSTEP + NWHH) {
        int j = i - NPRE - NSTEP;
        int n = j / HH, k = j - n * HH;
        float v = W_h_w[n * 2 * HH + HH + k];
        split1(v, Whh_hi[n * LDX + k], Whh_lo[n * LDX + k]);
    } else if (i < NPRE + NSTEP + NWHH + 1350) {
        int n = i - NPRE - NSTEP - NWHH;
        bias[n] = (n < HH) ? W_z_b[n]
                : (n < 2 * HH) ? W_h_b[n - HH]
                : U_r_b[n - 2 * HH];
    }
}

__global__ void gather_fe_kernel(const float* __restrict__ emb,
                                 const int* __restrict__ fnode,
                                 float* __restrict__ fe) {
    int i = blockIdx.x * blockDim.x + threadIdx.x;
    if (i >= NNODES * HH) return;
    int r = i / HH, c = i - r * HH;
    fe[i] = emb[fnode[r] * HH + c];
}

__global__ void gather_x_kernel(const float* __restrict__ fe,
                                const int* __restrict__ fmess,
                                __nv_bfloat16* __restrict__ xhi,
                                __nv_bfloat16* __restrict__ xlo) {
    int i = blockIdx.x * blockDim.x + threadIdx.x;
    if (i >= NMESS * HH) return;
    int r = i / HH, c = i - r * HH;
    float v = fe[fmess[r] * HH + c];
    split1(v, xhi[(size_t)r * LDX + c], xlo[(size_t)r * LDX + c]);
}

#define C2 225

// step 0: h = mask * sigmoid(xz) * tanh(xh); writes ZEROS when depth < 1
// (replaces the old zero_kernel — h pads never leak into real outputs).
__global__ void step0_kernel(const float* __restrict__ xzrh,
                             float* __restrict__ h,
                             __nv_bfloat16* __restrict__ hhi,
                             __nv_bfloat16* __restrict__ hlo,
                             const int* __restrict__ depthp) {
    int d = depthp ? __ldg(depthp) : MAXDEPTH;
    int i = blockIdx.x * blockDim.x + threadIdx.x;
    if (i >= NMESS * C2) return;
    int m = i / C2, c = i - m * C2;
    float2 v = make_float2(0.f, 0.f);
    if (d >= 1 && m != 0) {
        const float2* xp = (const float2*)xzrh + (size_t)m * (LDPRE / 2);
        float2 zv = sigm2(xp[c]);
        float2 ph = tanh2(xp[C2 + c]);
        v = make_float2(zv.x * ph.x, zv.y * ph.y);
    }
    size_t o = (size_t)m * (LDX / 2) + c;
    ((float2*)h)[o] = v;
    __nv_bfloat162 hi2, lo2;
    split1(v.x, hi2.x, lo2.x);
    split1(v.y, hi2.y, lo2.y);
    ((__nv_bfloat162*)hhi)[o] = hi2;
    ((__nv_bfloat162*)hlo)[o] = lo2;
}

__global__ void step_gather_kernel(const float* __restrict__ h,
                                   const float* __restrict__ hZU,
                                   const float* __restrict__ xzrh,
                                   const int* __restrict__ mg,
                                   float* __restrict__ sumh,
                                   float* __restrict__ z,
                                   __nv_bfloat16* __restrict__ sghi,
                                   __nv_bfloat16* __restrict__ sglo,
                                   const int* __restrict__ depthp, int step) {
    if (depthp && step >= __ldg(depthp)) return;
    int i = blockIdx.x * blockDim.x + threadIdx.x;
    if (i >= NMESS * C2) return;
    int m = i / C2, c = i - m * C2;
    const float2* xp = (const float2*)xzrh + (size_t)m * (LDPRE / 2);
    float2 xr = xp[2 * C2 + c];
    float2 sh = make_float2(0.f, 0.f);
    float2 sz = make_float2(0.f, 0.f);
    float2 sg = make_float2(0.f, 0.f);
    int idx[KNB];
#pragma unroll
    for (int k = 0; k < KNB; k++) idx[k] = mg[m * KNB + k];
#pragma unroll
    for (int k = 0; k < KNB; k++) {
        int j = idx[k];
        float2 hv = ((const float2*)h)[(size_t)j * (LDX / 2) + c];
        float2 zz = ((const float2*)hZU)[(size_t)j * (LDZU / 2) + c];
        float2 uu = ((const float2*)hZU)[(size_t)j * (LDZU / 2) + C2 + c];
        sh.x += hv.x; sh.y += hv.y;
        sz.x += zz.x; sz.y += zz.y;
        sg.x += hv.x / (1.f + __expf(-(xr.x + uu.x)));
        sg.y += hv.y / (1.f + __expf(-(xr.y + uu.y)));
    }
    size_t o = (size_t)m * (LDX / 2) + c;
    ((float2*)sumh)[o] = sh;
    float2 xz = xp[c];
    ((float2*)z)[o] = sigm2(make_float2(sz.x + xz.x, sz.y + xz.y));
    __nv_bfloat162 hi2, lo2;
    split1(sg.x, hi2.x, lo2.x);
    split1(sg.y, hi2.y, lo2.y);
    ((__nv_bfloat162*)sghi)[o] = hi2;
    ((__nv_bfloat162*)sglo)[o] = lo2;
}

__global__ void readout_kernel(const float* __restrict__ fe,
                               const float* __restrict__ h,
                               const int* __restrict__ root,
                               const int* __restrict__ ng,
                               float* __restrict__ rv) {
    int i = blockIdx.x * blockDim.x + threadIdx.x;
    if (i >= BB * HH) return;
    int b = i / HH, c = i - b * HH;
    int node = root[b];
    rv[b * 2 * HH + c] = fe[node * HH + c];
    float s = 0.f;
#pragma unroll
    for (int k = 0; k < KNB; k++)
        s += h[(size_t)ng[node * KNB + k] * LDX + c];
    rv[b * 2 * HH + HH + c] = s;
}

__global__ void score_kernel(const float* __restrict__ h2,
                             const float* __restrict__ w,
                             const float* __restrict__ b3,
                             float* __restrict__ out) {
    int gt = blockIdx.x * blockDim.x + threadIdx.x;
    int warp = gt >> 5, lane = gt & 31;
    if (warp >= BB) return;
    float s = 0.f;
    for (int k = lane; k < DHH; k += 32) s += h2[warp * DHH + k] * w[k];
#pragma unroll
    for (int o = 16; o; o >>= 1) s += __shfl_xor_sync(0xffffffffu, s, o);
    if (lane == 0) out[warp] = s + b3[0];
}

// ----------------- bf16 HMMA GEMM, pre-split operands ----------------------
// CTA tile 128(M) x 64(N), 8 warps as 4M x 2N of 32x32 warp tiles.
// K walked in chunks of 16, 3-stage cp.async ring, ONE sync per stage.
// acc = Alo@Bhi^T + Ahi@Blo^T + Ahi@Bhi^T over K=480.
// mode 0: C = acc.  mode 1: C = acc + bias[n].  mode 3: fused GRU h-update.
__global__ __launch_bounds__(256, 4)
void mma_gemm(const __nv_bfloat16* __restrict__ Ah,
              const __nv_bfloat16* __restrict__ Al,
              const __nv_bfloat16* __restrict__ Bh,
              const __nv_bfloat16* __restrict__ Bl,
              int mode,
              const float* __restrict__ pre,
              const float* __restrict__ biasp,
              const float* __restrict__ z,
              const float* __restrict__ sumh,
              float* __restrict__ C, int ldc,
              __nv_bfloat16* __restrict__ hhi,
              __nv_bfloat16* __restrict__ hlo,
              const int* __restrict__ depthp, int step) {
    if (depthp && step >= __ldg(depthp)) return;

    extern __shared__ __align__(16) char smem[];
    const uint32_t sb = smem_u32(smem);
    const int tid = threadIdx.x;
    const int warp = tid >> 5;
    const int wm = warp & 3;    // 4 x 32-row quarters
    const int wn = warp >> 2;   // 2 x 32-col halves
    const int bm = blockIdx.y * 128;
    const int bn = blockIdx.x * 64;

    wmma::fragment<wmma::accumulator, 16, 16, 16, float> acc[2][2];
#pragma unroll
    for (int i = 0; i < 2; i++)
#pragma unroll
        for (int j = 0; j < 2; j++) wmma::fill_fragment(acc[i][j], 0.f);

    // per-stage loader: 3 x CP16 per thread
    auto load_stage = [&](int stg, int kc) {
        uint32_t base = sb + (uint32_t)stg * STAGE;
        {
            int row = tid >> 1, q = tid & 1;
            uint32_t so = (uint32_t)(row * KPADB + q * 8) * 2;
            size_t ao = (size_t)(bm + row) * LDX + kc + q * 8;
            CP16(base + so,       Ah + ao);
            CP16(base + AOP + so, Al + ao);
        }
        {
            int op = tid >> 7, r = (tid & 127) >> 1, q = tid & 1;
            uint32_t so = (uint32_t)(r * KPADB + q * 8) * 2;
            size_t bo = (size_t)(bn + r) * LDX + kc + q * 8;
            CP16(base + 2 * AOP + op * BOP + so, (op ? Bl : Bh) + bo);
        }
    };

    auto do_mma = [&](int stg) {
        const __nv_bfloat16* SAh = (const __nv_bfloat16*)(smem + (size_t)stg * STAGE);
        const __nv_bfloat16* SAl = (const __nv_bfloat16*)(smem + (size_t)stg * STAGE + AOP);
        const __nv_bfloat16* SBh = (const __nv_bfloat16*)(smem + (size_t)stg * STAGE + 2 * AOP);
        const __nv_bfloat16* SBl = (const __nv_bfloat16*)(smem + (size_t)stg * STAGE + 2 * AOP + BOP);
        wmma::fragment<wmma::matrix_b, 16, 16, 16, __nv_bfloat16,
                       wmma::col_major> bhi[2], blo[2];
#pragma unroll
        for (int j = 0; j < 2; j++) {
            wmma::load_matrix_sync(bhi[j], SBh + (wn * 32 + j * 16) * KPADB, KPADB);
            wmma::load_matrix_sync(blo[j], SBl + (wn * 32 + j * 16) * KPADB, KPADB);
        }
#pragma unroll
        for (int i = 0; i < 2; i++) {
            wmma::fragment<wmma::matrix_a, 16, 16, 16, __nv_bfloat16,
                           wmma::row_major> ahi, alo;
            wmma::load_matrix_sync(ahi, SAh + (wm * 32 + i * 16) * KPADB, KPADB);
            wmma::load_matrix_sync(alo, SAl + (wm * 32 + i * 16) * KPADB, KPADB);
#pragma unroll
            for (int j = 0; j < 2; j++) {
                wmma::mma_sync(acc[i][j], alo, bhi[j], acc[i][j]);
                wmma::mma_sync(acc[i][j], ahi, blo[j], acc[i][j]);
                wmma::mma_sync(acc[i][j], ahi, bhi[j], acc[i][j]);
            }
        }
    };

    load_stage(0, 0);
    CP_COMMIT;
    load_stage(1, KC);
    CP_COMMIT;
    for (int ch = 0; ch < NT2; ch++) {
        if (ch + 1 < NT2) { CP_WAIT1; } else { CP_WAIT0; }
        __syncthreads();
        if (ch + 2 < NT2) {
            load_stage((ch + 2) % 3, (ch + 2) * KC);
            CP_COMMIT;
        }
        do_mma(ch % 3);
    }
    __syncthreads();

    if (mode == 0) {
#pragma unroll
        for (int i = 0; i < 2; i++)
#pragma unroll
            for (int j = 0; j < 2; j++) {
                float* cp = C + (size_t)(bm + wm * 32 + i * 16) * ldc
                              + bn + wn * 32 + j * 16;
                wmma::store_matrix_sync(cp, acc[i][j], ldc, wmma::mem_row_major);
            }
    } else {
        float* Cs = (float*)smem;
#pragma unroll
        for (int i = 0; i < 2; i++)
#pragma unroll
            for (int j = 0; j < 2; j++) {
                float* cp = Cs + (size_t)(wm * 32 + i * 16) * 68
                               + wn * 32 + j * 16;
                wmma::store_matrix_sync(cp, acc[i][j], 68, wmma::mem_row_major);
            }
        __syncthreads();
        int n = bn + (tid & 63);
        int quarter = tid >> 6;
        if (mode == 1) {
            float bv = biasp[n];
            for (int r = 0; r < 32; r++) {
                int row = quarter * 32 + r;
                int m = bm + row;
                C[(size_t)m * ldc + n] = Cs[(size_t)row * 68 + (tid & 63)] + bv;
            }
        } else if (n < HH) {
            for (int r = 0; r < 32; r++) {
                int row = quarter * 32 + r;
                int m = bm + row;
                float accv = Cs[(size_t)row * 68 + (tid & 63)];
                float ph = tanhf(accv + pre[(size_t)m * LDPRE + n]);
                float zv = z[(size_t)m * LDX + n];
                float sh = sumh[(size_t)m * LDX + n];
                float v = (1.f - zv) * sh + zv * ph;
                if (m == 0) v = 0.f;
                C[(size_t)m * ldc + n] = v;
                __nv_bfloat16 hv, lv;
                split1(v, hv, lv);
                hhi[(size_t)m * LDX + n] = hv;
                hlo[(size_t)m * LDX + n] = lv;
            }
        }
    }
}

// ------------------ fp32 SIMT GEMM (discriminator only) --------------------
#define BM 64
#define BN 64
#define BKK 16
#define TMs 4
#define TNs 4

__global__ __launch_bounds__(256)
void disc_gemm(const float* __restrict__ A, int lda,
               const float* __restrict__ W, int ldw,
               int M, int N, int K,
               const float* __restrict__ bias,
               float* __restrict__ C, int ldc) {
    __shared__ float As[BKK][BM];
    __shared__ float Ws[BKK][BN];
    int bm = blockIdx.y * BM, bn = blockIdx.x * BN;
    int tid = threadIdx.x;
    int tr = tid >> 4, tc = tid & 15;
    float acc[TMs][TNs];
#pragma unroll
    for (int i = 0; i < TMs; i++)
#pragma unroll
        for (int j = 0; j < TNs; j++) acc[i][j] = 0.f;
    for (int k0 = 0; k0 < K; k0 += BKK) {
#pragma unroll
        for (int t = 0; t < 4; t++) {
            int l = tid + t * 256;
            int i = l >> 4, j = l & 15;
            int gm = bm + i, gk = k0 + j;
            As[j][i] = (gm < M && gk < K) ? A[(size_t)gm * lda + gk] : 0.f;
        }
#pragma unroll
        for (int t = 0; t < 4; t++) {
            int l = tid + t * 256;
            int i = l >> 4, j = l & 15;
            int gn = bn + i, gk = k0 + j;
            Ws[j][i] = (gn < N && gk < K) ? W[(size_t)gn * ldw + gk] : 0.f;
        }
        __syncthreads();
#pragma unroll
        for (int kk = 0; kk < BKK; kk++) {
            float a[TMs], w[TNs];
#pragma unroll
            for (int i = 0; i < TMs; i++) a[i] = As[kk][tr * TMs + i];
#pragma unroll
            for (int j = 0; j < TNs; j++) w[j] = Ws[kk][tc * TNs + j];
#pragma unroll
            for (int i = 0; i < TMs; i++)
#pragma unroll
                for (int j = 0; j < TNs; j++) acc[i][j] += a[i] * w[j];
        }
        __syncthreads();
    }
#pragma unroll
    for (int i = 0; i < TMs; i++) {
        int m = bm + tr * TMs + i;
        if (m >= M) continue;
#pragma unroll
        for (int j = 0; j < TNs; j++) {
            int n = bn + tc * TNs + j;
            if (n >= N) continue;
            float v = acc[i][j] + bias[n];
            v = (v > 0.f) ? v : 0.1f * v;
            C[(size_t)m * ldc + n] = v;
        }
    }
}

// ------------------------------- launcher ----------------------------------
extern "C" void kernel_launch(void* const* d_in, const int* in_sizes, int n_in,
                              void* d_out, int out_size) {
    const int*   fnode      = (const int*)d_in[0];
    const int*   fmess      = (const int*)d_in[1];
    const int*   node_graph = (const int*)d_in[2];
    const int*   mess_graph = (const int*)d_in[3];
    const int*   root_idx   = (const int*)d_in[4];
    const float* emb        = (const float*)d_in[5];
    const float* W_z_w      = (const float*)d_in[6];
    const float* W_z_b      = (const float*)d_in[7];
    const float* W_r_w      = (const float*)d_in[8];
    const float* U_r_w      = (const float*)d_in[9];
    const float* U_r_b      = (const float*)d_in[10];
    const float* W_h_w      = (const float*)d_in[11];
    const float* W_h_b      = (const float*)d_in[12];
    const float* D1_w       = (const float*)d_in[13];
    const float* D1_b       = (const float*)d_in[14];
    const float* D2_w       = (const float*)d_in[15];
    const float* D2_b       = (const float*)d_in[16];
    const float* D3_w       = (const float*)d_in[17];
    const float* D3_b       = (const float*)d_in[18];
    const int*   depthp     = (n_in > 19) ? (const int*)d_in[19] : nullptr;
    float*       out        = (float*)d_out;

    float *fe, *xzrh, *h, *hZU, *sumh, *z, *bias, *rv, *d1, *d2;
    __nv_bfloat16 *xhi, *xlo, *hhi, *hlo, *sghi, *sglo;
    __nv_bfloat16 *Wpre_hi, *Wpre_lo, *Wstep_hi, *Wstep_lo, *Whh_hi, *Whh_lo;
    cudaGetSymbolAddress((void**)&fe,       g_fe);
    cudaGetSymbolAddress((void**)&xzrh,     g_xzrh);
    cudaGetSymbolAddress((void**)&h,        g_h);
    cudaGetSymbolAddress((void**)&hZU,      g_hZU);
    cudaGetSymbolAddress((void**)&sumh,     g_sumh);
    cudaGetSymbolAddress((void**)&z,        g_z);
    cudaGetSymbolAddress((void**)&bias,     g_bias);
    cudaGetSymbolAddress((void**)&rv,       g_rv);
    cudaGetSymbolAddress((void**)&d1,       g_d1);
    cudaGetSymbolAddress((void**)&d2,       g_d2);
    cudaGetSymbolAddress((void**)&xhi,      g_xhi);
    cudaGetSymbolAddress((void**)&xlo,      g_xlo);
    cudaGetSymbolAddress((void**)&hhi,      g_hhi);
    cudaGetSymbolAddress((void**)&hlo,      g_hlo);
    cudaGetSymbolAddress((void**)&sghi,     g_sghi);
    cudaGetSymbolAddress((void**)&sglo,     g_sglo);
    cudaGetSymbolAddress((void**)&Wpre_hi,  g_Wpre_hi);
    cudaGetSymbolAddress((void**)&Wpre_lo,  g_Wpre_lo);
    cudaGetSymbolAddress((void**)&Wstep_hi, g_Wstep_hi);
    cudaGetSymbolAddress((void**)&Wstep_lo, g_Wstep_lo);
    cudaGetSymbolAddress((void**)&Whh_hi,   g_Whh_hi);
    cudaGetSymbolAddress((void**)&Whh_lo,   g_Whh_lo);

    cudaFuncSetAttribute(mma_gemm,
                         cudaFuncAttributeMaxDynamicSharedMemorySize, SMTOT);

    const int TPB = 256;

    // launch 0: pack
    {
        int n = 1350 * HH + 900 * HH + HH * HH + 1350;
        pack_kernel<<<(n + TPB - 1) / TPB, TPB>>>(W_z_w, W_h_w, W_r_w, U_r_w,
                                                  W_z_b, W_h_b, U_r_b,
                                                  Wpre_hi, Wpre_lo,
                                                  Wstep_hi, Wstep_lo,
                                                  Whh_hi, Whh_lo, bias);
    }
    // launches 1,2: gathers
    gather_fe_kernel<<<(NNODES * HH + TPB - 1) / TPB, TPB>>>(emb, fnode, fe);
    gather_x_kernel<<<(NMESS * HH + TPB - 1) / TPB, TPB>>>(fe, fmess, xhi, xlo);

    // launch 3 (ncu profiles #3): pre-GEMM with bias epilogue
    mma_gemm<<<dim3(22, 47), 256, SMTOT>>>(xhi, xlo, Wpre_hi, Wpre_lo, 1,
        nullptr, bias, nullptr, nullptr, xzrh, LDPRE,
        nullptr, nullptr, nullptr, 0);

    // launch 4: step 0 (also handles depth==0 by writing zeros)
    step0_kernel<<<(NMESS * C2 + TPB - 1) / TPB, TPB>>>(xzrh, h, hhi, hlo, depthp);

    for (int s = 1; s < MAXDEPTH; s++) {
        mma_gemm<<<dim3(15, 47), 256, SMTOT>>>(hhi, hlo, Wstep_hi, Wstep_lo, 0,
            nullptr, nullptr, nullptr, nullptr, hZU, LDZU,
            nullptr, nullptr, depthp, s);
        step_gather_kernel<<<(NMESS * C2 + TPB - 1) / TPB, TPB>>>(
            h, hZU, xzrh, mess_graph, sumh, z, sghi, sglo, depthp, s);
        mma_gemm<<<dim3(8, 47), 256, SMTOT>>>(sghi, sglo, Whh_hi, Whh_lo, 3,
            xzrh + HH, nullptr, z, sumh, h, LDX,
            hhi, hlo, depthp, s);
    }

    readout_kernel<<<(BB * HH + TPB - 1) / TPB, TPB>>>(fe, h, root_idx, node_graph, rv);
    disc_gemm<<<dim3((DHH + BN - 1) / BN, (BB + BM - 1) / BM), 256>>>(
        rv, 2 * HH, D1_w, 2 * HH, BB, DHH, 2 * HH, D1_b, d1, DHH);
    disc_gemm<<<dim3((DHH + BN - 1) / BN, (BB + BM - 1) / BM), 256>>>(
        d1, DHH, D2_w, DHH, BB, DHH, DHH, D2_b, d2, DHH);
    score_kernel<<<(BB * 32 + TPB - 1) / TPB, TPB>>>(d2, D3_w, D3_b, out);
}

// round 16
// speedup vs baseline: 1.5047x; 1.5047x over previous
#include <cuda_runtime.h>
#include <cuda_bf16.h>
#include <cstdint>
#include <math.h>
#include <mma.h>

using namespace nvcuda;

// ---------------------------------------------------------------------------
// ScaffoldGAN JTNN GRU + discriminator. R16: REVERT to R14's proven GEMM
// (K-chunk 32, 2-stage, 128x64 CTA, 32x32 warp tiles, (256,3)); R15's K=16
// 3-stage ring regressed (fragment-load amortization >> occupancy).
// Kept from R15: zero_kernel deleted (step0 writes zeros when depth<1).
// ---------------------------------------------------------------------------

#define HH     450
#define NNODES 4000
#define NMESS  6000
#define KNB    6
#define BB     256
#define DHH    450
#define MAXDEPTH 15
#define MROWS  6016

#define LDX   512
#define LDZU  1024
#define LDPRE 1536

#define NTILE 15          // K = 480 = 15 x 32
#define KPADB 40          // bf16 elems per smem row (80 B)
#define STGA  10240       // A operand: 128*KPADB*2
#define STGB  5120        // B operand:  64*KPADB*2
#define STAGE 30720
#define SMTOT 61440       // 2 stages; epilogue Cs (128*68*4) fits

// ---------------- device scratch (zero-initialized; pads never written) ----
__device__ float g_fe[NNODES * HH];
__device__ float g_xzrh[MROWS * LDPRE];   // (xz+bz) | (xh+bh) | (xr+bUr)
__device__ float g_h[MROWS * LDX];
__device__ float g_hZU[MROWS * LDZU];
__device__ float g_sumh[MROWS * LDX];
__device__ float g_z[MROWS * LDX];
__device__ float g_bias[1536];
__device__ float g_rv[BB * 2 * HH];
__device__ float g_d1[BB * DHH];
__device__ float g_d2[BB * DHH];
__device__ __nv_bfloat16 g_xhi[MROWS * LDX];
__device__ __nv_bfloat16 g_xlo[MROWS * LDX];
__device__ __nv_bfloat16 g_hhi[MROWS * LDX];
__device__ __nv_bfloat16 g_hlo[MROWS * LDX];
__device__ __nv_bfloat16 g_sghi[MROWS * LDX];
__device__ __nv_bfloat16 g_sglo[MROWS * LDX];
__device__ __nv_bfloat16 g_Wpre_hi[1408 * LDX];
__device__ __nv_bfloat16 g_Wpre_lo[1408 * LDX];
__device__ __nv_bfloat16 g_Wstep_hi[1024 * LDX];
__device__ __nv_bfloat16 g_Wstep_lo[1024 * LDX];
__device__ __nv_bfloat16 g_Whh_hi[512 * LDX];
__device__ __nv_bfloat16 g_Whh_lo[512 * LDX];

// --------------------------- helpers ---------------------------------------
__device__ __forceinline__ uint32_t smem_u32(const void* p) {
    uint32_t a;
    asm("{ .reg .u64 t; cvta.to.shared.u64 t, %1; cvt.u32.u64 %0, t; }"
        : "=r"(a) : "l"(p));
    return a;
}
#define CP16(d, s) \
    asm volatile("cp.async.cg.shared.global [%0], [%1], 16;" \
                 :: "r"(d), "l"(s) : "memory")
#define CP_COMMIT asm volatile("cp.async.commit_group;" ::: "memory")
#define CP_WAIT1  asm volatile("cp.async.wait_group 1;" ::: "memory")
#define CP_WAIT0  asm volatile("cp.async.wait_group 0;" ::: "memory")

__device__ __forceinline__ void split1(float v, __nv_bfloat16& hi, __nv_bfloat16& lo) {
    hi = __float2bfloat16(v);
    lo = __float2bfloat16(v - __bfloat162float(hi));
}
__device__ __forceinline__ float2 sigm2(float2 v) {
    return make_float2(1.f / (1.f + __expf(-v.x)), 1.f / (1.f + __expf(-v.y)));
}
__device__ __forceinline__ float2 tanh2(float2 v) {
    return make_float2(tanhf(v.x), tanhf(v.y));
}

// ---------------------------- small kernels --------------------------------
__global__ void pack_kernel(const float* __restrict__ W_z_w,
                            const float* __restrict__ W_h_w,
                            const float* __restrict__ W_r_w,
                            const float* __restrict__ U_r_w,
                            const float* __restrict__ W_z_b,
                            const float* __restrict__ W_h_b,
                            const float* __restrict__ U_r_b,
                            __nv_bfloat16* __restrict__ Wpre_hi,
                            __nv_bfloat16* __restrict__ Wpre_lo,
                            __nv_bfloat16* __restrict__ Wstep_hi,
                            __nv_bfloat16* __restrict__ Wstep_lo,
                            __nv_bfloat16* __restrict__ Whh_hi,
                            __nv_bfloat16* __restrict__ Whh_lo,
                            float* __restrict__ bias) {
    int i = blockIdx.x * blockDim.x + threadIdx.x;
    const int NPRE  = 1350 * HH;
    const int NSTEP = 900 * HH;
    const int NWHH  = HH * HH;
    if (i < NPRE) {
        int n = i / HH, k = i - n * HH;
        float v;
        if (n < HH)            v = W_z_w[n * 2 * HH + k];
        else if (n < 2 * HH)   v = W_h_w[(n - HH) * 2 * HH + k];
        else                   v = W_r_w[(n - 2 * HH) * HH + k];
        split1(v, Wpre_hi[n * LDX + k], Wpre_lo[n * LDX + k]);
    } else if (i < NPRE + NSTEP) {
        int j = i - NPRE;
        int n = j / HH, k = j - n * HH;
        float v = (n < HH) ? W_z_w[n * 2 * HH + HH + k]
                           : U_r_w[(n - HH) * HH + k];
        split1(v, Wstep_hi[n * LDX + k], Wstep_lo[n * LDX + k]);
    } else if (i < NPRE + NSTEP + NWHH) {
        int j = i - NPRE - NSTEP;
        int n = j / HH, k = j - n * HH;
        float v = W_h_w[n * 2 * HH + HH + k];
        split1(v, Whh_hi[n * LDX + k], Whh_lo[n * LDX + k]);
    } else if (i < NPRE + NSTEP + NWHH + 1350) {
        int n = i - NPRE - NSTEP - NWHH;
        bias[n] = (n < HH) ? W_z_b[n]
                : (n < 2 * HH) ? W_h_b[n - HH]
                : U_r_b[n - 2 * HH];
    }
}

__global__ void gather_fe_kernel(const float* __restrict__ emb,
                                 const int* __restrict__ fnode,
                                 float* __restrict__ fe) {
    int i = blockIdx.x * blockDim.x + threadIdx.x;
    if (i >= NNODES * HH) return;
    int r = i / HH, c = i - r * HH;
    fe[i] = emb[fnode[r] * HH + c];
}

__global__ void gather_x_kernel(const float* __restrict__ fe,
                                const int* __restrict__ fmess,
                                __nv_bfloat16* __restrict__ xhi,
                                __nv_bfloat16* __restrict__ xlo) {
    int i = blockIdx.x * blockDim.x + threadIdx.x;
    if (i >= NMESS * HH) return;
    int r = i / HH, c = i - r * HH;
    float v = fe[fmess[r] * HH + c];
    split1(v, xhi[(size_t)r * LDX + c], xlo[(size_t)r * LDX + c]);
}

#define C2 225

// step 0: h = mask * sigmoid(xz) * tanh(xh); writes ZEROS when depth < 1.
__global__ void step0_kernel(const float* __restrict__ xzrh,
                             float* __restrict__ h,
                             __nv_bfloat16* __restrict__ hhi,
                             __nv_bfloat16* __restrict__ hlo,
                             const int* __restrict__ depthp) {
    int d = depthp ? __ldg(depthp) : MAXDEPTH;
    int i = blockIdx.x * blockDim.x + threadIdx.x;
    if (i >= NMESS * C2) return;
    int m = i / C2, c = i - m * C2;
    float2 v = make_float2(0.f, 0.f);
    if (d >= 1 && m != 0) {
        const float2* xp = (const float2*)xzrh + (size_t)m * (LDPRE / 2);
        float2 zv = sigm2(xp[c]);
        float2 ph = tanh2(xp[C2 + c]);
        v = make_float2(zv.x * ph.x, zv.y * ph.y);
    }
    size_t o = (size_t)m * (LDX / 2) + c;
    ((float2*)h)[o] = v;
    __nv_bfloat162 hi2, lo2;
    split1(v.x, hi2.x, lo2.x);
    split1(v.y, hi2.y, lo2.y);
    ((__nv_bfloat162*)hhi)[o] = hi2;
    ((__nv_bfloat162*)hlo)[o] = lo2;
}

__global__ void step_gather_kernel(const float* __restrict__ h,
                                   const float* __restrict__ hZU,
                                   const float* __restrict__ xzrh,
                                   const int* __restrict__ mg,
                                   float* __restrict__ sumh,
                                   float* __restrict__ z,
                                   __nv_bfloat16* __restrict__ sghi,
                                   __nv_bfloat16* __restrict__ sglo,
                                   const int* __restrict__ depthp, int step) {
    if (depthp && step >= __ldg(depthp)) return;
    int i = blockIdx.x * blockDim.x + threadIdx.x;
    if (i >= NMESS * C2) return;
    int m = i / C2, c = i - m * C2;
    const float2* xp = (const float2*)xzrh + (size_t)m * (LDPRE / 2);
    float2 xr = xp[2 * C2 + c];
    float2 sh = make_float2(0.f, 0.f);
    float2 sz = make_float2(0.f, 0.f);
    float2 sg = make_float2(0.f, 0.f);
    int idx[KNB];
#pragma unroll
    for (int k = 0; k < KNB; k++) idx[k] = mg[m * KNB + k];
#pragma unroll
    for (int k = 0; k < KNB; k++) {
        int j = idx[k];
        float2 hv = ((const float2*)h)[(size_t)j * (LDX / 2) + c];
        float2 zz = ((const float2*)hZU)[(size_t)j * (LDZU / 2) + c];
        float2 uu = ((const float2*)hZU)[(size_t)j * (LDZU / 2) + C2 + c];
        sh.x += hv.x; sh.y += hv.y;
        sz.x += zz.x; sz.y += zz.y;
        sg.x += hv.x / (1.f + __expf(-(xr.x + uu.x)));
        sg.y += hv.y / (1.f + __expf(-(xr.y + uu.y)));
    }
    size_t o = (size_t)m * (LDX / 2) + c;
    ((float2*)sumh)[o] = sh;
    float2 xz = xp[c];
    ((float2*)z)[o] = sigm2(make_float2(sz.x + xz.x, sz.y + xz.y));
    __nv_bfloat162 hi2, lo2;
    split1(sg.x, hi2.x, lo2.x);
    split1(sg.y, hi2.y, lo2.y);
    ((__nv_bfloat162*)sghi)[o] = hi2;
    ((__nv_bfloat162*)sglo)[o] = lo2;
}

__global__ void readout_kernel(const float* __restrict__ fe,
                               const float* __restrict__ h,
                               const int* __restrict__ root,
                               const int* __restrict__ ng,
                               float* __restrict__ rv) {
    int i = blockIdx.x * blockDim.x + threadIdx.x;
    if (i >= BB * HH) return;
    int b = i / HH, c = i - b * HH;
    int node = root[b];
    rv[b * 2 * HH + c] = fe[node * HH + c];
    float s = 0.f;
#pragma unroll
    for (int k = 0; k < KNB; k++)
        s += h[(size_t)ng[node * KNB + k] * LDX + c];
    rv[b * 2 * HH + HH + c] = s;
}

__global__ void score_kernel(const float* __restrict__ h2,
                             const float* __restrict__ w,
                             const float* __restrict__ b3,
                             float* __restrict__ out) {
    int gt = blockIdx.x * blockDim.x + threadIdx.x;
    int warp = gt >> 5, lane = gt & 31;
    if (warp >= BB) return;
    float s = 0.f;
    for (int k = lane; k < DHH; k += 32) s += h2[warp * DHH + k] * w[k];
#pragma unroll
    for (int o = 16; o; o >>= 1) s += __shfl_xor_sync(0xffffffffu, s, o);
    if (lane == 0) out[warp] = s + b3[0];
}

// ----------------- bf16 HMMA GEMM, pre-split operands ----------------------
// CTA tile 128(M) x 64(N); 8 warps as 4M x 2N of 32x32 warp tiles.
// K-chunk 32, 2-stage double buffer (R14 proven config).
// acc = Alo@Bhi^T + Ahi@Blo^T + Ahi@Bhi^T over K=480.
// mode 0: C = acc.  mode 1: C = acc + bias[n].  mode 3: fused GRU h-update.
__global__ __launch_bounds__(256, 3)
void mma_gemm(const __nv_bfloat16* __restrict__ Ah,
              const __nv_bfloat16* __restrict__ Al,
              const __nv_bfloat16* __restrict__ Bh,
              const __nv_bfloat16* __restrict__ Bl,
              int mode,
              const float* __restrict__ pre,
              const float* __restrict__ biasp,
              const float* __restrict__ z,
              const float* __restrict__ sumh,
              float* __restrict__ C, int ldc,
              __nv_bfloat16* __restrict__ hhi,
              __nv_bfloat16* __restrict__ hlo,
              const int* __restrict__ depthp, int step) {
    if (depthp && step >= __ldg(depthp)) return;

    extern __shared__ __align__(16) char smem[];
    const uint32_t sb = smem_u32(smem);
    const int tid = threadIdx.x;
    const int warp = tid >> 5;
    const int wm = warp & 3;    // 4 x 32-row quarters
    const int wn = warp >> 2;   // 2 x 32-col halves
    const int bm = blockIdx.y * 128;
    const int bn = blockIdx.x * 64;

    wmma::fragment<wmma::accumulator, 16, 16, 16, float> acc[2][2];
#pragma unroll
    for (int i = 0; i < 2; i++)
#pragma unroll
        for (int j = 0; j < 2; j++) wmma::fill_fragment(acc[i][j], 0.f);

    auto load_stage = [&](int stg, int kc) {
        uint32_t base = sb + (uint32_t)stg * STAGE;
#pragma unroll
        for (int t = 0; t < 2; t++) {
            int u = tid + t * 256;
            int row = u >> 2, q = u & 3;
            uint32_t so = (uint32_t)(row * KPADB + q * 8) * 2;
            size_t ao = (size_t)(bm + row) * LDX + kc + q * 8;
            CP16(base + so,        Ah + ao);
            CP16(base + STGA + so, Al + ao);
        }
        {
            int row = tid >> 2, q = tid & 3;
            uint32_t so = (uint32_t)(row * KPADB + q * 8) * 2;
            size_t bo = (size_t)(bn + row) * LDX + kc + q * 8;
            CP16(base + 2 * STGA + so,        Bh + bo);
            CP16(base + 2 * STGA + STGB + so, Bl + bo);
        }
    };

    auto do_mma = [&](int stg) {
        const __nv_bfloat16* SAh = (const __nv_bfloat16*)(smem + (size_t)stg * STAGE);
        const __nv_bfloat16* SAl = (const __nv_bfloat16*)(smem + (size_t)stg * STAGE + STGA);
        const __nv_bfloat16* SBh = (const __nv_bfloat16*)(smem + (size_t)stg * STAGE + 2 * STGA);
        const __nv_bfloat16* SBl = (const __nv_bfloat16*)(smem + (size_t)stg * STAGE + 2 * STGA + STGB);
#pragma unroll
        for (int kk = 0; kk < 32; kk += 16) {
            wmma::fragment<wmma::matrix_b, 16, 16, 16, __nv_bfloat16,
                           wmma::col_major> bhi[2], blo[2];
#pragma unroll
            for (int j = 0; j < 2; j++) {
                wmma::load_matrix_sync(bhi[j], SBh + (wn * 32 + j * 16) * KPADB + kk, KPADB);
                wmma::load_matrix_sync(blo[j], SBl + (wn * 32 + j * 16) * KPADB + kk, KPADB);
            }
#pragma unroll
            for (int i = 0; i < 2; i++) {
                wmma::fragment<wmma::matrix_a, 16, 16, 16, __nv_bfloat16,
                               wmma::row_major> ahi, alo;
                wmma::load_matrix_sync(ahi, SAh + (wm * 32 + i * 16) * KPADB + kk, KPADB);
                wmma::load_matrix_sync(alo, SAl + (wm * 32 + i * 16) * KPADB + kk, KPADB);
#pragma unroll
                for (int j = 0; j < 2; j++) {
                    wmma::mma_sync(acc[i][j], alo, bhi[j], acc[i][j]);
                    wmma::mma_sync(acc[i][j], ahi, blo[j], acc[i][j]);
                    wmma::mma_sync(acc[i][j], ahi, bhi[j], acc[i][j]);
                }
            }
        }
    };

    load_stage(0, 0);
    CP_COMMIT;
    for (int ch = 0; ch < NTILE; ch++) {
        if (ch + 1 < NTILE) {
            load_stage((ch + 1) & 1, (ch + 1) * 32);
            CP_COMMIT;
            CP_WAIT1;
        } else {
            CP_WAIT0;
        }
        __syncthreads();
        do_mma(ch & 1);
        __syncthreads();
    }

    if (mode == 0) {
#pragma unroll
        for (int i = 0; i < 2; i++)
#pragma unroll
            for (int j = 0; j < 2; j++) {
                float* cp = C + (size_t)(bm + wm * 32 + i * 16) * ldc
                              + bn + wn * 32 + j * 16;
                wmma::store_matrix_sync(cp, acc[i][j], ldc, wmma::mem_row_major);
            }
    } else {
        float* Cs = (float*)smem;
#pragma unroll
        for (int i = 0; i < 2; i++)
#pragma unroll
            for (int j = 0; j < 2; j++) {
                float* cp = Cs + (size_t)(wm * 32 + i * 16) * 68
                               + wn * 32 + j * 16;
                wmma::store_matrix_sync(cp, acc[i][j], 68, wmma::mem_row_major);
            }
        __syncthreads();
        int n = bn + (tid & 63);
        int quarter = tid >> 6;
        if (mode == 1) {
            float bv = biasp[n];
            for (int r = 0; r < 32; r++) {
                int row = quarter * 32 + r;
                int m = bm + row;
                C[(size_t)m * ldc + n] = Cs[(size_t)row * 68 + (tid & 63)] + bv;
            }
        } else if (n < HH) {
            for (int r = 0; r < 32; r++) {
                int row = quarter * 32 + r;
                int m = bm + row;
                float accv = Cs[(size_t)row * 68 + (tid & 63)];
                float ph = tanhf(accv + pre[(size_t)m * LDPRE + n]);
                float zv = z[(size_t)m * LDX + n];
                float sh = sumh[(size_t)m * LDX + n];
                float v = (1.f - zv) * sh + zv * ph;
                if (m == 0) v = 0.f;
                C[(size_t)m * ldc + n] = v;
                __nv_bfloat16 hv, lv;
                split1(v, hv, lv);
                hhi[(size_t)m * LDX + n] = hv;
                hlo[(size_t)m * LDX + n] = lv;
            }
        }
    }
}

// ------------------ fp32 SIMT GEMM (discriminator only) --------------------
#define BM 64
#define BN 64
#define BKK 16
#define TMs 4
#define TNs 4

__global__ __launch_bounds__(256)
void disc_gemm(const float* __restrict__ A, int lda,
               const float* __restrict__ W, int ldw,
               int M, int N, int K,
               const float* __restrict__ bias,
               float* __restrict__ C, int ldc) {
    __shared__ float As[BKK][BM];
    __shared__ float Ws[BKK][BN];
    int bm = blockIdx.y * BM, bn = blockIdx.x * BN;
    int tid = threadIdx.x;
    int tr = tid >> 4, tc = tid & 15;
    float acc[TMs][TNs];
#pragma unroll
    for (int i = 0; i < TMs; i++)
#pragma unroll
        for (int j = 0; j < TNs; j++) acc[i][j] = 0.f;
    for (int k0 = 0; k0 < K; k0 += BKK) {
#pragma unroll
        for (int t = 0; t < 4; t++) {
            int l = tid + t * 256;
            int i = l >> 4, j = l & 15;
            int gm = bm + i, gk = k0 + j;
            As[j][i] = (gm < M && gk < K) ? A[(size_t)gm * lda + gk] : 0.f;
        }
#pragma unroll
        for (int t = 0; t < 4; t++) {
            int l = tid + t * 256;
            int i = l >> 4, j = l & 15;
            int gn = bn + i, gk = k0 + j;
            Ws[j][i] = (gn < N && gk < K) ? W[(size_t)gn * ldw + gk] : 0.f;
        }
        __syncthreads();
#pragma unroll
        for (int kk = 0; kk < BKK; kk++) {
            float a[TMs], w[TNs];
#pragma unroll
            for (int i = 0; i < TMs; i++) a[i] = As[kk][tr * TMs + i];
#pragma unroll
            for (int j = 0; j < TNs; j++) w[j] = Ws[kk][tc * TNs + j];
#pragma unroll
            for (int i = 0; i < TMs; i++)
#pragma unroll
                for (int j = 0; j < TNs; j++) acc[i][j] += a[i] * w[j];
        }
        __syncthreads();
    }
#pragma unroll
    for (int i = 0; i < TMs; i++) {
        int m = bm + tr * TMs + i;
        if (m >= M) continue;
#pragma unroll
        for (int j = 0; j < TNs; j++) {
            int n = bn + tc * TNs + j;
            if (n >= N) continue;
            float v = acc[i][j] + bias[n];
            v = (v > 0.f) ? v : 0.1f * v;
            C[(size_t)m * ldc + n] = v;
        }
    }
}

// ------------------------------- launcher ----------------------------------
extern "C" void kernel_launch(void* const* d_in, const int* in_sizes, int n_in,
                              void* d_out, int out_size) {
    const int*   fnode      = (const int*)d_in[0];
    const int*   fmess      = (const int*)d_in[1];
    const int*   node_graph = (const int*)d_in[2];
    const int*   mess_graph = (const int*)d_in[3];
    const int*   root_idx   = (const int*)d_in[4];
    const float* emb        = (const float*)d_in[5];
    const float* W_z_w      = (const float*)d_in[6];
    const float* W_z_b      = (const float*)d_in[7];
    const float* W_r_w      = (const float*)d_in[8];
    const float* U_r_w      = (const float*)d_in[9];
    const float* U_r_b      = (const float*)d_in[10];
    const float* W_h_w      = (const float*)d_in[11];
    const float* W_h_b      = (const float*)d_in[12];
    const float* D1_w       = (const float*)d_in[13];
    const float* D1_b       = (const float*)d_in[14];
    const float* D2_w       = (const float*)d_in[15];
    const float* D2_b       = (const float*)d_in[16];
    const float* D3_w       = (const float*)d_in[17];
    const float* D3_b       = (const float*)d_in[18];
    const int*   depthp     = (n_in > 19) ? (const int*)d_in[19] : nullptr;
    float*       out        = (float*)d_out;

    float *fe, *xzrh, *h, *hZU, *sumh, *z, *bias, *rv, *d1, *d2;
    __nv_bfloat16 *xhi, *xlo, *hhi, *hlo, *sghi, *sglo;
    __nv_bfloat16 *Wpre_hi, *Wpre_lo, *Wstep_hi, *Wstep_lo, *Whh_hi, *Whh_lo;
    cudaGetSymbolAddress((void**)&fe,       g_fe);
    cudaGetSymbolAddress((void**)&xzrh,     g_xzrh);
    cudaGetSymbolAddress((void**)&h,        g_h);
    cudaGetSymbolAddress((void**)&hZU,      g_hZU);
    cudaGetSymbolAddress((void**)&sumh,     g_sumh);
    cudaGetSymbolAddress((void**)&z,        g_z);
    cudaGetSymbolAddress((void**)&bias,     g_bias);
    cudaGetSymbolAddress((void**)&rv,       g_rv);
    cudaGetSymbolAddress((void**)&d1,       g_d1);
    cudaGetSymbolAddress((void**)&d2,       g_d2);
    cudaGetSymbolAddress((void**)&xhi,      g_xhi);
    cudaGetSymbolAddress((void**)&xlo,      g_xlo);
    cudaGetSymbolAddress((void**)&hhi,      g_hhi);
    cudaGetSymbolAddress((void**)&hlo,      g_hlo);
    cudaGetSymbolAddress((void**)&sghi,     g_sghi);
    cudaGetSymbolAddress((void**)&sglo,     g_sglo);
    cudaGetSymbolAddress((void**)&Wpre_hi,  g_Wpre_hi);
    cudaGetSymbolAddress((void**)&Wpre_lo,  g_Wpre_lo);
    cudaGetSymbolAddress((void**)&Wstep_hi, g_Wstep_hi);
    cudaGetSymbolAddress((void**)&Wstep_lo, g_Wstep_lo);
    cudaGetSymbolAddress((void**)&Whh_hi,   g_Whh_hi);
    cudaGetSymbolAddress((void**)&Whh_lo,   g_Whh_lo);

    cudaFuncSetAttribute(mma_gemm,
                         cudaFuncAttributeMaxDynamicSharedMemorySize, SMTOT);

    const int TPB = 256;

    // launch 0: pack
    {
        int n = 1350 * HH + 900 * HH + HH * HH + 1350;
        pack_kernel<<<(n + TPB - 1) / TPB, TPB>>>(W_z_w, W_h_w, W_r_w, U_r_w,
                                                  W_z_b, W_h_b, U_r_b,
                                                  Wpre_hi, Wpre_lo,
                                                  Wstep_hi, Wstep_lo,
                                                  Whh_hi, Whh_lo, bias);
    }
    // launches 1,2: gathers
    gather_fe_kernel<<<(NNODES * HH + TPB - 1) / TPB, TPB>>>(emb, fnode, fe);
    gather_x_kernel<<<(NMESS * HH + TPB - 1) / TPB, TPB>>>(fe, fmess, xhi, xlo);

    // launch 3 (ncu profiles #3): pre-GEMM with bias epilogue
    mma_gemm<<<dim3(22, 47), 256, SMTOT>>>(xhi, xlo, Wpre_hi, Wpre_lo, 1,
        nullptr, bias, nullptr, nullptr, xzrh, LDPRE,
        nullptr, nullptr, nullptr, 0);

    // launch 4: step 0 (writes zeros when depth==0; replaces zero_kernel)
    step0_kernel<<<(NMESS * C2 + TPB - 1) / TPB, TPB>>>(xzrh, h, hhi, hlo, depthp);

    for (int s = 1; s < MAXDEPTH; s++) {
        mma_gemm<<<dim3(15, 47), 256, SMTOT>>>(hhi, hlo, Wstep_hi, Wstep_lo, 0,
            nullptr, nullptr, nullptr, nullptr, hZU, LDZU,
            nullptr, nullptr, depthp, s);
        step_gather_kernel<<<(NMESS * C2 + TPB - 1) / TPB, TPB>>>(
            h, hZU, xzrh, mess_graph, sumh, z, sghi, sglo, depthp, s);
        mma_gemm<<<dim3(8, 47), 256, SMTOT>>>(sghi, sglo, Whh_hi, Whh_lo, 3,
            xzrh + HH, nullptr, z, sumh, h, LDX,
            hhi, hlo, depthp, s);
    }

    readout_kernel<<<(BB * HH + TPB - 1) / TPB, TPB>>>(fe, h, root_idx, node_graph, rv);
    disc_gemm<<<dim3((DHH + BN - 1) / BN, (BB + BM - 1) / BM), 256>>>(
        rv, 2 * HH, D1_w, 2 * HH, BB, DHH, 2 * HH, D1_b, d1, DHH);
    disc_gemm<<<dim3((DHH + BN - 1) / BN, (BB + BM - 1) / BM), 256>>>(
        d1, DHH, D2_w, DHH, BB, DHH, DHH, D2_b, d2, DHH);
    score_kernel<<<(BB * 32 + TPB - 1) / TPB, TPB>>>(d2, D3_w, D3_b, out);
}